// round 9
// baseline (speedup 1.0000x reference)
#include <cuda_runtime.h>

#define J3 768
#define NC 256

__device__ __align__(16) unsigned g_wqkvT2[J3 * NC]; // W^T: [j][c] tf32 bits
__device__ __align__(16) uint4 g_wprojP[16384];      // [cc 0..15][ktG 0..31][lane]
__device__ __align__(16) unsigned g_qkv[(size_t)1024 * 128 * J3];
__device__ __align__(16) unsigned g_o[(size_t)1024 * 128 * NC];

__device__ __forceinline__ unsigned f2tf(float f) {
    unsigned u; asm("cvt.rna.tf32.f32 %0, %1;" : "=r"(u) : "f"(f)); return u;
}
__device__ __forceinline__ float ex2(float x) {
    float y; asm("ex2.approx.f32 %0, %1;" : "=f"(y) : "f"(x)); return y;
}
__device__ __forceinline__ unsigned sptr(const void* p) {
    return (unsigned)__cvta_generic_to_shared(p);
}
__device__ __forceinline__ void cp16(unsigned dst, const void* src) {
    asm volatile("cp.async.ca.shared.global [%0], [%1], 16;\n" :: "r"(dst), "l"(src));
}
__device__ __forceinline__ void cp_commit() { asm volatile("cp.async.commit_group;\n"); }
template<int N> __device__ __forceinline__ void cp_wait() {
    asm volatile("cp.async.wait_group %0;\n" :: "n"(N));
}
// ldmatrix x4: mats of 8 rows x 16B; within each mat lane l <- 32-bit elem (l/4, l%4)
__device__ __forceinline__ void ldsm4(unsigned* r, unsigned addr) {
    asm volatile("ldmatrix.sync.aligned.m8n8.x4.shared.b16 {%0,%1,%2,%3}, [%4];"
        : "=r"(r[0]), "=r"(r[1]), "=r"(r[2]), "=r"(r[3]) : "r"(addr));
}
// m16n8k8 tf32: A row-major a0=[g][q] a1=[g+8][q] a2=[g][q+4] a3=[g+8][q+4]
// B col-major b0=B[q][g] b1=B[q+4][g]; C c0=(g,2q) c1=(g,2q+1) c2/c3 rows +8
__device__ __forceinline__ void mma8(float* c, const unsigned* a, unsigned b0, unsigned b1) {
    asm volatile(
        "mma.sync.aligned.m16n8k8.row.col.f32.tf32.tf32.f32 "
        "{%0,%1,%2,%3},{%4,%5,%6,%7},{%8,%9},{%0,%1,%2,%3};\n"
        : "+f"(c[0]), "+f"(c[1]), "+f"(c[2]), "+f"(c[3])
        : "r"(a[0]), "r"(a[1]), "r"(a[2]), "r"(a[3]), "r"(b0), "r"(b1));
}

__global__ void k_prep(const float* __restrict__ Wqkv, const float* __restrict__ Wproj) {
    int i = blockIdx.x * 256 + threadIdx.x;        // 0..212991
    if (i < J3 * NC) {
        int j = i >> 8, c = i & 255;               // Wqkv[c][j] -> W^T[j][c]
        g_wqkvT2[i] = f2tf(Wqkv[c * J3 + j]);
    } else {
        int ii = i - J3 * NC;                      // 0..16383
        int lane = ii & 31, g = lane >> 2, q = lane & 3;
        int e = ii >> 5, ktG = e & 31, cc = e >> 5;
        int c0 = cc * 16, k0 = ktG * 8;
        uint4 u;
        u.x = f2tf(Wproj[(k0 + q) * NC + c0 + g]);
        u.y = f2tf(Wproj[(k0 + q) * NC + c0 + g + 8]);
        u.z = f2tf(Wproj[(k0 + q + 4) * NC + c0 + g]);
        u.w = f2tf(Wproj[(k0 + q + 4) * NC + c0 + g + 8]);
        g_wprojP[ii] = u;
    }
}

// ---------- QKV projection: per (t,b) CTA: D[j 768][w 128] = W^T x + bias
// Weights streamed via cp.async double-buffered [128j][64c] tiles; direct STG epilogue.
__global__ void __launch_bounds__(512) k_qkv(const float* __restrict__ x,
                                             const float* __restrict__ bqkv) {
    extern __shared__ unsigned sh[];
    unsigned* Xs = sh;                 // [256][136] tf32 (B operand)
    unsigned* Wt = sh + 256 * 136;     // 2 x [128][68] (A operand tiles)
    const int t = blockIdx.x, b = blockIdx.y;
    const int tid = threadIdx.x, lane = tid & 31, wid = tid >> 5;
    const int g = lane >> 2, q = lane & 3;
    const int wm = wid >> 2, wn = wid & 3;
    const int arow = lane & 15, acolo = (lane >> 4) << 2;

    // weight chunk issue: chunk = jb*4 + ck; tile rows j in jb block, cols ck*64..+63
    const int wjr = tid >> 2, wseg = tid & 3;      // 4 threads per row, 4 cp16 each
    auto issue_chunk = [&](int chunk) {
        int jb = chunk >> 2, ck = chunk & 3;
        unsigned bufp = sptr(Wt + (chunk & 1) * 128 * 68 + wjr * 68 + wseg * 16);
        const unsigned* src = g_wqkvT2 + (jb * 128 + wjr) * NC + ck * 64 + wseg * 16;
        #pragma unroll
        for (int k = 0; k < 4; k++) cp16(bufp + k * 16, src + k * 4);
    };
    issue_chunk(0); cp_commit();
    issue_chunk(1); cp_commit();

    const float* xb = x + ((size_t)b * NC * 128 + t) * 128;
    #pragma unroll
    for (int p = 0; p < 16; p++) {
        int l = tid + p * 512;
        int c = l >> 5, col = (l & 31) * 4;
        float4 v = *(const float4*)(xb + (size_t)c * 16384 + col);
        uint4 u = { f2tf(v.x), f2tf(v.y), f2tf(v.z), f2tf(v.w) };
        *(uint4*)(Xs + c * 136 + col) = u;
    }
    __syncthreads();                   // Xs ready

    for (int jb = 0; jb < 6; jb++) {
        float acc[2][4][4];
        #pragma unroll
        for (int mt = 0; mt < 2; mt++)
            #pragma unroll
            for (int nt = 0; nt < 4; nt++)
                #pragma unroll
                for (int i = 0; i < 4; i++) acc[mt][nt][i] = 0.f;

        for (int ck = 0; ck < 4; ck++) {
            const int chunk = jb * 4 + ck;
            // tail: at the final chunk nothing newer is outstanding, so wait<1>
            // would pass with THIS chunk still in flight. Drain fully there.
            if (chunk == 23) cp_wait<0>(); else cp_wait<1>();
            __syncthreads();           // chunk's tile visible to all
            unsigned* buf = Wt + (chunk & 1) * 128 * 68;
            #pragma unroll
            for (int kk = 0; kk < 8; kk++) {
                unsigned a0[4], a1[4];
                ldsm4(a0, sptr(buf + (wm * 32 + arow) * 68 + kk * 8 + acolo));
                ldsm4(a1, sptr(buf + (wm * 32 + 16 + arow) * 68 + kk * 8 + acolo));
                const int c0 = ck * 64 + kk * 8;
                unsigned b0[4], b1[4];
                #pragma unroll
                for (int nt = 0; nt < 4; nt++) {
                    int w = wn * 32 + nt * 8 + g;
                    b0[nt] = Xs[(c0 + q) * 136 + w];
                    b1[nt] = Xs[(c0 + q + 4) * 136 + w];
                }
                #pragma unroll
                for (int nt = 0; nt < 4; nt++) {
                    mma8(acc[0][nt], a0, b0[nt], b1[nt]);
                    mma8(acc[1][nt], a1, b0[nt], b1[nt]);
                }
            }
            __syncthreads();           // tile consumed; buffer free for reuse
            if (chunk + 2 < 24) { issue_chunk(chunk + 2); cp_commit(); }
        }

        // direct epilogue: g_qkv[((b*128+w)*128+t)*J3 + j] = tf32(acc + bias)
        const int jbase = jb * 128 + wm * 32;
        float bl[2][2];
        #pragma unroll
        for (int mt = 0; mt < 2; mt++) {
            bl[mt][0] = bqkv[jbase + mt * 16 + g];
            bl[mt][1] = bqkv[jbase + mt * 16 + g + 8];
        }
        #pragma unroll
        for (int mt = 0; mt < 2; mt++)
            #pragma unroll
            for (int nt = 0; nt < 4; nt++) {
                int w0 = wn * 32 + nt * 8 + 2 * q;
                unsigned* r0 = g_qkv + ((size_t)((b * 128 + w0) * 128 + t)) * J3
                               + jbase + mt * 16 + g;
                unsigned* r1 = r0 + (size_t)128 * J3;      // w0+1: stride is 128*J3, not J3
                r0[0] = f2tf(acc[mt][nt][0] + bl[mt][0]);
                r1[0] = f2tf(acc[mt][nt][1] + bl[mt][0]);
                r0[8] = f2tf(acc[mt][nt][2] + bl[mt][1]);
                r1[8] = f2tf(acc[mt][nt][3] + bl[mt][1]);
            }
    }
}

// ---------- attention per (head, s)
__global__ void __launch_bounds__(256) k_attn() {
    extern __shared__ unsigned sh[];
    unsigned* Qs = sh;                 // [128][68]
    unsigned* Ks = sh + 128 * 68;      // [128][68]
    unsigned* Vs = sh + 2 * 128 * 68;  // [128][72]
    const int head = blockIdx.x, s = blockIdx.y;
    const int tid = threadIdx.x, lane = tid & 31, wid = tid >> 5;
    const int g = lane >> 2, q = lane & 3;
    const int lsel = lane >> 3;
    const int arow = lane & 15, acolo = (lane >> 4) << 2;

    const unsigned* base = g_qkv + (size_t)s * 128 * J3 + head * 64;
    const int r0 = tid >> 4, l16 = tid & 15;
    for (int tt = r0; tt < 128; tt += 16) {        // group 0: Q + K
        const unsigned* row = base + (size_t)tt * J3;
        cp16(sptr(Qs + tt * 68 + l16 * 4), row + l16 * 4);
        cp16(sptr(Ks + tt * 68 + l16 * 4), row + 256 + l16 * 4);
    }
    cp_commit();
    for (int tt = r0; tt < 128; tt += 16) {        // group 1: V
        const unsigned* row = base + (size_t)tt * J3;
        cp16(sptr(Vs + tt * 72 + l16 * 4), row + 512 + l16 * 4);
    }
    cp_commit();
    cp_wait<1>();                                  // Q,K ready; V still in flight
    __syncthreads();

    const int m0 = wid * 16;
    float sa[16][4];
    #pragma unroll
    for (int nt = 0; nt < 16; nt++)
        #pragma unroll
        for (int i = 0; i < 4; i++) sa[nt][i] = 0.f;

    #pragma unroll
    for (int kt = 0; kt < 8; kt++) {
        unsigned a[4];
        ldsm4(a, sptr(Qs + (m0 + arow) * 68 + kt * 8 + acolo));
        #pragma unroll
        for (int p = 0; p < 8; p++) {
            unsigned bb[4];
            int ntl = p * 2 + (lsel >> 1);
            ldsm4(bb, sptr(Ks + (ntl * 8 + (lane & 7)) * 68 + kt * 8 + ((lsel & 1) << 2)));
            mma8(sa[p * 2],     a, bb[0], bb[1]);
            mma8(sa[p * 2 + 1], a, bb[2], bb[3]);
        }
    }

    // softmax: rows g (sa[][0,1]) and g+8 (sa[][2,3]); reduce across quad (q)
    const float k2e = 0.125f * 1.4426950408889634f;
    float mx0 = -1e30f, mx1 = -1e30f;
    #pragma unroll
    for (int nt = 0; nt < 16; nt++) {
        mx0 = fmaxf(mx0, fmaxf(sa[nt][0], sa[nt][1]));
        mx1 = fmaxf(mx1, fmaxf(sa[nt][2], sa[nt][3]));
    }
    mx0 = fmaxf(mx0, __shfl_xor_sync(0xffffffffu, mx0, 1));
    mx0 = fmaxf(mx0, __shfl_xor_sync(0xffffffffu, mx0, 2));
    mx1 = fmaxf(mx1, __shfl_xor_sync(0xffffffffu, mx1, 1));
    mx1 = fmaxf(mx1, __shfl_xor_sync(0xffffffffu, mx1, 2));
    float s0 = 0.f, s1 = 0.f;
    #pragma unroll
    for (int nt = 0; nt < 16; nt++) {
        sa[nt][0] = ex2((sa[nt][0] - mx0) * k2e);
        sa[nt][1] = ex2((sa[nt][1] - mx0) * k2e);
        sa[nt][2] = ex2((sa[nt][2] - mx1) * k2e);
        sa[nt][3] = ex2((sa[nt][3] - mx1) * k2e);
        s0 += sa[nt][0] + sa[nt][1];
        s1 += sa[nt][2] + sa[nt][3];
    }
    s0 += __shfl_xor_sync(0xffffffffu, s0, 1);
    s0 += __shfl_xor_sync(0xffffffffu, s0, 2);
    s1 += __shfl_xor_sync(0xffffffffu, s1, 1);
    s1 += __shfl_xor_sync(0xffffffffu, s1, 2);
    const float r0v = 1.f / s0, r1v = 1.f / s1;

    cp_wait<0>();                      // V ready
    __syncthreads();                   // all warps done with Qs/Ks; V visible
    unsigned* Ps = sh;                 // [128][132], overlays Qs+Ks
    #pragma unroll
    for (int nt = 0; nt < 16; nt++) {
        int cc = nt * 8 + 2 * q;
        Ps[(m0 + g) * 132 + cc]         = f2tf(sa[nt][0] * r0v);
        Ps[(m0 + g) * 132 + cc + 1]     = f2tf(sa[nt][1] * r0v);
        Ps[(m0 + g + 8) * 132 + cc]     = f2tf(sa[nt][2] * r1v);
        Ps[(m0 + g + 8) * 132 + cc + 1] = f2tf(sa[nt][3] * r1v);
    }
    __syncwarp();                      // warp reads only its own P rows

    float oa[8][4];
    #pragma unroll
    for (int nt = 0; nt < 8; nt++)
        #pragma unroll
        for (int i = 0; i < 4; i++) oa[nt][i] = 0.f;

    #pragma unroll
    for (int kt = 0; kt < 16; kt++) {
        unsigned a[4];
        ldsm4(a, sptr(Ps + (m0 + arow) * 132 + kt * 8 + acolo));
        #pragma unroll
        for (int nt = 0; nt < 8; nt++) {
            unsigned b0 = Vs[(kt * 8 + q) * 72 + nt * 8 + g];
            unsigned b1 = Vs[(kt * 8 + q + 4) * 72 + nt * 8 + g];
            mma8(oa[nt], a, b0, b1);
        }
    }

    unsigned* ob = g_o + (size_t)s * 128 * NC + head * 64;
    #pragma unroll
    for (int nt = 0; nt < 8; nt++) {
        int d0 = nt * 8 + 2 * q;
        uint2 u0 = { f2tf(oa[nt][0]), f2tf(oa[nt][1]) };
        uint2 u1 = { f2tf(oa[nt][2]), f2tf(oa[nt][3]) };
        *(uint2*)(ob + (size_t)(m0 + g) * NC + d0) = u0;
        *(uint2*)(ob + (size_t)(m0 + g + 8) * NC + d0) = u1;
    }
}

// ---------- output projection: per (t,b) CTA, cp.async double-buffered O staging
__global__ void __launch_bounds__(512) k_proj(const float* __restrict__ bproj,
                                              float* __restrict__ out) {
    extern __shared__ unsigned sh[];   // 2 x [128][132]
    const int t = blockIdx.x, b = blockIdx.y;
    const int tid = threadIdx.x, lane = tid & 31, wid = tid >> 5;
    const int g = lane >> 2, q = lane & 3;
    const int wm = wid >> 2, wn = wid & 3;
    const int lsel = lane >> 3;

    #pragma unroll
    for (int kh = 0; kh < 2; kh++) {
        unsigned* shb = sh + kh * 128 * 132;
        #pragma unroll
        for (int p = 0; p < 8; p++) {
            int l = tid + p * 512;
            int w = l >> 5, col = (l & 31) * 4;
            cp16(sptr(shb + w * 132 + col),
                 g_o + ((size_t)((b * 128 + w) * 128 + t)) * NC + kh * 128 + col);
        }
        cp_commit();
    }

    float acc[4][4][4];
    #pragma unroll
    for (int mt = 0; mt < 4; mt++)
        #pragma unroll
        for (int nt = 0; nt < 4; nt++)
            #pragma unroll
            for (int i = 0; i < 4; i++) acc[mt][nt][i] = 0.f;

    cp_wait<1>();
    __syncthreads();

    for (int kh = 0; kh < 2; kh++) {
        unsigned* shb = sh + kh * 128 * 132;
        #pragma unroll 2
        for (int kt = 0; kt < 16; kt++) {
            uint4 af[4];
            #pragma unroll
            for (int mt = 0; mt < 4; mt++)
                af[mt] = g_wprojP[((wm * 4 + mt) * 32 + kh * 16 + kt) * 32 + lane];
            #pragma unroll
            for (int p = 0; p < 2; p++) {
                unsigned bb[4];
                int ntl = p * 2 + (lsel >> 1);
                ldsm4(bb, sptr(shb + (wn * 32 + ntl * 8 + (lane & 7)) * 132
                                  + kt * 8 + ((lsel & 1) << 2)));
                #pragma unroll
                for (int mt = 0; mt < 4; mt++) {
                    mma8(acc[mt][p * 2],     (const unsigned*)&af[mt], bb[0], bb[1]);
                    mma8(acc[mt][p * 2 + 1], (const unsigned*)&af[mt], bb[2], bb[3]);
                }
            }
        }
        if (kh == 0) { cp_wait<0>(); __syncthreads(); }
    }

    #pragma unroll
    for (int mt = 0; mt < 4; mt++) {
        int c0 = wm * 64 + mt * 16 + g;
        float bi0 = bproj[c0], bi1 = bproj[c0 + 8];
        #pragma unroll
        for (int nt = 0; nt < 4; nt++) {
            int w0 = wn * 32 + nt * 8 + 2 * q;
            float2 v0 = { acc[mt][nt][0] + bi0, acc[mt][nt][1] + bi0 };
            float2 v1 = { acc[mt][nt][2] + bi1, acc[mt][nt][3] + bi1 };
            *(float2*)(out + ((size_t)(b * NC + c0) * 128 + t) * 128 + w0) = v0;
            *(float2*)(out + ((size_t)(b * NC + c0 + 8) * 128 + t) * 128 + w0) = v1;
        }
    }
}

extern "C" void kernel_launch(void* const* d_in, const int* in_sizes, int n_in,
                              void* d_out, int out_size) {
    const float* x     = (const float*)d_in[0];
    const float* Wqkv  = (const float*)d_in[1];
    const float* bqkv  = (const float*)d_in[2];
    const float* Wproj = (const float*)d_in[3];
    const float* bproj = (const float*)d_in[4];
    float* out = (float*)d_out;

    cudaFuncSetAttribute(k_qkv,  cudaFuncAttributeMaxDynamicSharedMemorySize, 208896);
    cudaFuncSetAttribute(k_attn, cudaFuncAttributeMaxDynamicSharedMemorySize, 106496);
    cudaFuncSetAttribute(k_proj, cudaFuncAttributeMaxDynamicSharedMemorySize, 135168);

    k_prep<<<832, 256>>>(Wqkv, Wproj);
    k_qkv<<<dim3(128, 8), 512, 208896>>>(x, bqkv);
    k_attn<<<dim3(4, 1024), 256, 106496>>>();
    k_proj<<<dim3(128, 8), 512, 135168>>>(bproj, out);
}

// round 10
// speedup vs baseline: 1.2902x; 1.2902x over previous
#include <cuda_runtime.h>

#define J3 768
#define NC 256

__device__ __align__(16) uint4 g_wqkvP[49152];   // [jj 0..47][kt 0..31][lane] frag {a0,a1,a2,a3}
__device__ __align__(16) uint4 g_wprojP[16384];  // [cc 0..15][ktG 0..31][lane]
__device__ __align__(16) unsigned g_qkv[(size_t)1024 * 128 * J3];
__device__ __align__(16) unsigned g_o[(size_t)1024 * 128 * NC];

__device__ __forceinline__ unsigned f2tf(float f) {
    unsigned u; asm("cvt.rna.tf32.f32 %0, %1;" : "=r"(u) : "f"(f)); return u;
}
__device__ __forceinline__ float ex2(float x) {
    float y; asm("ex2.approx.f32 %0, %1;" : "=f"(y) : "f"(x)); return y;
}
__device__ __forceinline__ unsigned sptr(const void* p) {
    return (unsigned)__cvta_generic_to_shared(p);
}
__device__ __forceinline__ void cp16(unsigned dst, const void* src) {
    asm volatile("cp.async.ca.shared.global [%0], [%1], 16;\n" :: "r"(dst), "l"(src));
}
__device__ __forceinline__ void cp_commit() { asm volatile("cp.async.commit_group;\n"); }
template<int N> __device__ __forceinline__ void cp_wait() {
    asm volatile("cp.async.wait_group %0;\n" :: "n"(N));
}
// ldmatrix x4: mats of 8 rows x 16B; within each mat lane l <- 32-bit elem (l/4, l%4)
__device__ __forceinline__ void ldsm4(unsigned* r, unsigned addr) {
    asm volatile("ldmatrix.sync.aligned.m8n8.x4.shared.b16 {%0,%1,%2,%3}, [%4];"
        : "=r"(r[0]), "=r"(r[1]), "=r"(r[2]), "=r"(r[3]) : "r"(addr));
}
// m16n8k8 tf32: A row-major a0=[g][q] a1=[g+8][q] a2=[g][q+4] a3=[g+8][q+4]
// B col-major b0=B[q][g] b1=B[q+4][g]; C c0=(g,2q) c1=(g,2q+1) c2/c3 rows +8
__device__ __forceinline__ void mma8(float* c, const unsigned* a, unsigned b0, unsigned b1) {
    asm volatile(
        "mma.sync.aligned.m16n8k8.row.col.f32.tf32.tf32.f32 "
        "{%0,%1,%2,%3},{%4,%5,%6,%7},{%8,%9},{%0,%1,%2,%3};\n"
        : "+f"(c[0]), "+f"(c[1]), "+f"(c[2]), "+f"(c[3])
        : "r"(a[0]), "r"(a[1]), "r"(a[2]), "r"(a[3]), "r"(b0), "r"(b1));
}

// Prepack weights into fragment-major uint4 so mainloop A-loads are single LDG.128.
__global__ void k_prep(const float* __restrict__ Wqkv, const float* __restrict__ Wproj) {
    int i = blockIdx.x * 256 + threadIdx.x;       // 0..65535
    int lane = i & 31, g = lane >> 2, q = lane & 3;
    if (i < 49152) {
        int e = i >> 5, kt = e & 31, jj = e >> 5;
        int j0 = jj * 16, c0 = kt * 8;
        uint4 u;
        u.x = f2tf(Wqkv[(c0 + q) * J3 + j0 + g]);
        u.y = f2tf(Wqkv[(c0 + q) * J3 + j0 + g + 8]);
        u.z = f2tf(Wqkv[(c0 + q + 4) * J3 + j0 + g]);
        u.w = f2tf(Wqkv[(c0 + q + 4) * J3 + j0 + g + 8]);
        g_wqkvP[i] = u;
    } else {
        int ii = i - 49152;                        // 0..16383
        int e = ii >> 5, ktG = e & 31, cc = e >> 5;
        int c0 = cc * 16, k0 = ktG * 8;
        uint4 u;
        u.x = f2tf(Wproj[(k0 + q) * NC + c0 + g]);
        u.y = f2tf(Wproj[(k0 + q) * NC + c0 + g + 8]);
        u.z = f2tf(Wproj[(k0 + q + 4) * NC + c0 + g]);
        u.w = f2tf(Wproj[(k0 + q + 4) * NC + c0 + g + 8]);
        g_wprojP[ii] = u;
    }
}

// ---------- QKV projection (R6 design): per (t,b,wh) CTA: D[j 768][w 64], 2 CTAs/SM
__global__ void __launch_bounds__(256, 2) k_qkv(const float* __restrict__ x,
                                                const float* __restrict__ bqkv) {
    extern __shared__ unsigned sh[];
    unsigned* Xs = sh;                        // [256][72]
    float* Ds = (float*)(sh + 256 * 72);      // [64][132]
    const int t = blockIdx.x, b = blockIdx.y, wh = blockIdx.z;
    const int tid = threadIdx.x, lane = tid & 31, wid = tid >> 5;
    const int g = lane >> 2, q = lane & 3;
    const int wm = wid >> 1, wn = wid & 1;

    const float* xb = x + ((size_t)b * NC * 128 + t) * 128 + wh * 64;
    #pragma unroll
    for (int p = 0; p < 16; p++) {
        int l = tid + p * 256;
        int c = l >> 4, col = (l & 15) * 4;
        float4 v = *(const float4*)(xb + (size_t)c * 16384 + col);
        unsigned* d = Xs + c * 72 + col;
        d[0] = f2tf(v.x); d[1] = f2tf(v.y); d[2] = f2tf(v.z); d[3] = f2tf(v.w);
    }
    __syncthreads();

    for (int jb = 0; jb < 6; jb++) {
        float acc[2][4][4];
        #pragma unroll
        for (int mt = 0; mt < 2; mt++)
            #pragma unroll
            for (int nt = 0; nt < 4; nt++)
                #pragma unroll
                for (int i = 0; i < 4; i++) acc[mt][nt][i] = 0.f;

        const int jj0 = jb * 8 + wm * 2;
        #pragma unroll 4
        for (int kt = 0; kt < 32; kt++) {
            uint4 af0 = g_wqkvP[(jj0 * 32 + kt) * 32 + lane];
            uint4 af1 = g_wqkvP[((jj0 + 1) * 32 + kt) * 32 + lane];
            unsigned b0[4], b1[4];
            #pragma unroll
            for (int nt = 0; nt < 4; nt++) {
                int w = wn * 32 + nt * 8 + g;
                b0[nt] = Xs[(kt * 8 + q) * 72 + w];
                b1[nt] = Xs[(kt * 8 + q + 4) * 72 + w];
            }
            #pragma unroll
            for (int nt = 0; nt < 4; nt++) {
                mma8(acc[0][nt], (const unsigned*)&af0, b0[nt], b1[nt]);
                mma8(acc[1][nt], (const unsigned*)&af1, b0[nt], b1[nt]);
            }
        }

        const int jbase = jb * 128 + wm * 32;
        float bl[2][2];
        #pragma unroll
        for (int mt = 0; mt < 2; mt++) {
            bl[mt][0] = bqkv[jbase + mt * 16 + g];
            bl[mt][1] = bqkv[jbase + mt * 16 + g + 8];
        }

        __syncthreads();   // prev jb's Ds fully consumed
        #pragma unroll
        for (int mt = 0; mt < 2; mt++)
            #pragma unroll
            for (int nt = 0; nt < 4; nt++) {
                int w0 = wn * 32 + nt * 8 + 2 * q;
                int jl = wm * 32 + mt * 16 + g;
                Ds[w0 * 132 + jl]           = acc[mt][nt][0] + bl[mt][0];
                Ds[(w0 + 1) * 132 + jl]     = acc[mt][nt][1] + bl[mt][0];
                Ds[w0 * 132 + jl + 8]       = acc[mt][nt][2] + bl[mt][1];
                Ds[(w0 + 1) * 132 + jl + 8] = acc[mt][nt][3] + bl[mt][1];
            }
        __syncthreads();

        #pragma unroll
        for (int p = 0; p < 8; p++) {
            int l = tid + p * 256;
            int w = l >> 5, col = (l & 31) * 4;
            float4 v = *(const float4*)(Ds + w * 132 + col);
            uint4 u = { f2tf(v.x), f2tf(v.y), f2tf(v.z), f2tf(v.w) };
            *(uint4*)(g_qkv + ((size_t)((b * 128 + wh * 64 + w) * 128 + t)) * J3
                      + jb * 128 + col) = u;
        }
    }
}

// ---------- attention per (head, s), 2 CTAs/SM
__global__ void __launch_bounds__(256, 2) k_attn() {
    extern __shared__ unsigned sh[];
    unsigned* Qs = sh;                 // [128][68]
    unsigned* Ks = sh + 128 * 68;      // [128][68]
    unsigned* Vs = sh + 2 * 128 * 68;  // [128][72]
    const int head = blockIdx.x, s = blockIdx.y;
    const int tid = threadIdx.x, lane = tid & 31, wid = tid >> 5;
    const int g = lane >> 2, q = lane & 3;
    const int lsel = lane >> 3;
    const int arow = lane & 15, acolo = (lane >> 4) << 2;

    const unsigned* base = g_qkv + (size_t)s * 128 * J3 + head * 64;
    const int r0 = tid >> 4, l16 = tid & 15;
    for (int tt = r0; tt < 128; tt += 16) {        // group 0: Q + K
        const unsigned* row = base + (size_t)tt * J3;
        cp16(sptr(Qs + tt * 68 + l16 * 4), row + l16 * 4);
        cp16(sptr(Ks + tt * 68 + l16 * 4), row + 256 + l16 * 4);
    }
    cp_commit();
    for (int tt = r0; tt < 128; tt += 16) {        // group 1: V
        const unsigned* row = base + (size_t)tt * J3;
        cp16(sptr(Vs + tt * 72 + l16 * 4), row + 512 + l16 * 4);
    }
    cp_commit();
    cp_wait<1>();                                  // Q,K ready; V still in flight
    __syncthreads();

    const int m0 = wid * 16;
    float sa[16][4];
    #pragma unroll
    for (int nt = 0; nt < 16; nt++)
        #pragma unroll
        for (int i = 0; i < 4; i++) sa[nt][i] = 0.f;

    #pragma unroll
    for (int kt = 0; kt < 8; kt++) {
        unsigned a[4];
        ldsm4(a, sptr(Qs + (m0 + arow) * 68 + kt * 8 + acolo));
        #pragma unroll
        for (int p = 0; p < 8; p++) {
            unsigned bb[4];
            int ntl = p * 2 + (lsel >> 1);
            ldsm4(bb, sptr(Ks + (ntl * 8 + (lane & 7)) * 68 + kt * 8 + ((lsel & 1) << 2)));
            mma8(sa[p * 2],     a, bb[0], bb[1]);
            mma8(sa[p * 2 + 1], a, bb[2], bb[3]);
        }
    }

    // softmax: rows g (sa[][0,1]) and g+8 (sa[][2,3]); reduce across quad (q)
    const float k2e = 0.125f * 1.4426950408889634f;
    float mx0 = -1e30f, mx1 = -1e30f;
    #pragma unroll
    for (int nt = 0; nt < 16; nt++) {
        mx0 = fmaxf(mx0, fmaxf(sa[nt][0], sa[nt][1]));
        mx1 = fmaxf(mx1, fmaxf(sa[nt][2], sa[nt][3]));
    }
    mx0 = fmaxf(mx0, __shfl_xor_sync(0xffffffffu, mx0, 1));
    mx0 = fmaxf(mx0, __shfl_xor_sync(0xffffffffu, mx0, 2));
    mx1 = fmaxf(mx1, __shfl_xor_sync(0xffffffffu, mx1, 1));
    mx1 = fmaxf(mx1, __shfl_xor_sync(0xffffffffu, mx1, 2));
    float s0 = 0.f, s1 = 0.f;
    #pragma unroll
    for (int nt = 0; nt < 16; nt++) {
        sa[nt][0] = ex2((sa[nt][0] - mx0) * k2e);
        sa[nt][1] = ex2((sa[nt][1] - mx0) * k2e);
        sa[nt][2] = ex2((sa[nt][2] - mx1) * k2e);
        sa[nt][3] = ex2((sa[nt][3] - mx1) * k2e);
        s0 += sa[nt][0] + sa[nt][1];
        s1 += sa[nt][2] + sa[nt][3];
    }
    s0 += __shfl_xor_sync(0xffffffffu, s0, 1);
    s0 += __shfl_xor_sync(0xffffffffu, s0, 2);
    s1 += __shfl_xor_sync(0xffffffffu, s1, 1);
    s1 += __shfl_xor_sync(0xffffffffu, s1, 2);
    const float r0v = 1.f / s0, r1v = 1.f / s1;

    cp_wait<0>();                      // V ready
    __syncthreads();                   // all warps done with Qs/Ks; V visible
    unsigned* Ps = sh;                 // [128][132], overlays Qs+Ks
    #pragma unroll
    for (int nt = 0; nt < 16; nt++) {
        int cc = nt * 8 + 2 * q;
        Ps[(m0 + g) * 132 + cc]         = f2tf(sa[nt][0] * r0v);
        Ps[(m0 + g) * 132 + cc + 1]     = f2tf(sa[nt][1] * r0v);
        Ps[(m0 + g + 8) * 132 + cc]     = f2tf(sa[nt][2] * r1v);
        Ps[(m0 + g + 8) * 132 + cc + 1] = f2tf(sa[nt][3] * r1v);
    }
    __syncwarp();                      // warp reads only its own P rows

    float oa[8][4];
    #pragma unroll
    for (int nt = 0; nt < 8; nt++)
        #pragma unroll
        for (int i = 0; i < 4; i++) oa[nt][i] = 0.f;

    #pragma unroll
    for (int kt = 0; kt < 16; kt++) {
        unsigned a[4];
        ldsm4(a, sptr(Ps + (m0 + arow) * 132 + kt * 8 + acolo));
        #pragma unroll
        for (int nt = 0; nt < 8; nt++) {
            unsigned b0 = Vs[(kt * 8 + q) * 72 + nt * 8 + g];
            unsigned b1 = Vs[(kt * 8 + q + 4) * 72 + nt * 8 + g];
            mma8(oa[nt], a, b0, b1);
        }
    }

    unsigned* ob = g_o + (size_t)s * 128 * NC + head * 64;
    #pragma unroll
    for (int nt = 0; nt < 8; nt++) {
        int d0 = nt * 8 + 2 * q;
        uint2 u0 = { f2tf(oa[nt][0]), f2tf(oa[nt][1]) };
        uint2 u1 = { f2tf(oa[nt][2]), f2tf(oa[nt][3]) };
        *(uint2*)(ob + (size_t)(m0 + g) * NC + d0) = u0;
        *(uint2*)(ob + (size_t)(m0 + g + 8) * NC + d0) = u1;
    }
}

// ---------- output projection: per (t,b,wh) CTA over 64 w, 2 CTAs/SM
__global__ void __launch_bounds__(256, 2) k_proj(const float* __restrict__ bproj,
                                                 float* __restrict__ out) {
    extern __shared__ unsigned sh[];   // 2 x [64][132]
    const int t = blockIdx.x, b = blockIdx.y, wh = blockIdx.z;
    const int tid = threadIdx.x, lane = tid & 31, wid = tid >> 5;
    const int g = lane >> 2, q = lane & 3;
    const int wm = wid >> 1, wn = wid & 1;
    const int lsel = lane >> 3;

    // prefetch both kh halves of the O tile [64 w][128 c each]
    #pragma unroll
    for (int kh = 0; kh < 2; kh++) {
        unsigned* shb = sh + kh * 64 * 132;
        #pragma unroll
        for (int p = 0; p < 8; p++) {
            int l = tid + p * 256;
            int w = l >> 5, col = (l & 31) * 4;
            cp16(sptr(shb + w * 132 + col),
                 g_o + ((size_t)((b * 128 + wh * 64 + w) * 128 + t)) * NC + kh * 128 + col);
        }
        cp_commit();
    }

    float acc[4][4][4];
    #pragma unroll
    for (int mt = 0; mt < 4; mt++)
        #pragma unroll
        for (int nt = 0; nt < 4; nt++)
            #pragma unroll
            for (int i = 0; i < 4; i++) acc[mt][nt][i] = 0.f;

    cp_wait<1>();
    __syncthreads();

    for (int kh = 0; kh < 2; kh++) {
        unsigned* shb = sh + kh * 64 * 132;
        #pragma unroll 2
        for (int kt = 0; kt < 16; kt++) {
            uint4 af[4];
            #pragma unroll
            for (int mt = 0; mt < 4; mt++)
                af[mt] = g_wprojP[((wm * 4 + mt) * 32 + kh * 16 + kt) * 32 + lane];
            #pragma unroll
            for (int p = 0; p < 2; p++) {
                unsigned bb[4];
                int ntl = p * 2 + (lsel >> 1);
                ldsm4(bb, sptr(shb + (wn * 32 + ntl * 8 + (lane & 7)) * 132
                                  + kt * 8 + ((lsel & 1) << 2)));
                #pragma unroll
                for (int mt = 0; mt < 4; mt++) {
                    mma8(acc[mt][p * 2],     (const unsigned*)&af[mt], bb[0], bb[1]);
                    mma8(acc[mt][p * 2 + 1], (const unsigned*)&af[mt], bb[2], bb[3]);
                }
            }
        }
        if (kh == 0) { cp_wait<0>(); __syncthreads(); }
    }

    #pragma unroll
    for (int mt = 0; mt < 4; mt++) {
        int c0 = wm * 64 + mt * 16 + g;
        float bi0 = bproj[c0], bi1 = bproj[c0 + 8];
        #pragma unroll
        for (int nt = 0; nt < 4; nt++) {
            int w0 = wh * 64 + wn * 32 + nt * 8 + 2 * q;
            float2 v0 = { acc[mt][nt][0] + bi0, acc[mt][nt][1] + bi0 };
            float2 v1 = { acc[mt][nt][2] + bi1, acc[mt][nt][3] + bi1 };
            *(float2*)(out + ((size_t)(b * NC + c0) * 128 + t) * 128 + w0) = v0;
            *(float2*)(out + ((size_t)(b * NC + c0 + 8) * 128 + t) * 128 + w0) = v1;
        }
    }
}

extern "C" void kernel_launch(void* const* d_in, const int* in_sizes, int n_in,
                              void* d_out, int out_size) {
    const float* x     = (const float*)d_in[0];
    const float* Wqkv  = (const float*)d_in[1];
    const float* bqkv  = (const float*)d_in[2];
    const float* Wproj = (const float*)d_in[3];
    const float* bproj = (const float*)d_in[4];
    float* out = (float*)d_out;

    cudaFuncSetAttribute(k_qkv,  cudaFuncAttributeMaxDynamicSharedMemorySize, 107520);
    cudaFuncSetAttribute(k_attn, cudaFuncAttributeMaxDynamicSharedMemorySize, 106496);
    cudaFuncSetAttribute(k_proj, cudaFuncAttributeMaxDynamicSharedMemorySize, 67584);

    k_prep<<<256, 256>>>(Wqkv, Wproj);
    k_qkv<<<dim3(128, 8, 2), 256, 107520>>>(x, bqkv);
    k_attn<<<dim3(4, 1024), 256, 106496>>>();
    k_proj<<<dim3(128, 8, 2), 256, 67584>>>(bproj, out);
}

// round 11
// speedup vs baseline: 1.3692x; 1.0612x over previous
#include <cuda_runtime.h>

#define J3 768
#define NC 256

__device__ __align__(16) uint4 g_wqkvP[49152];   // [jj 0..47][kt 0..31][lane] frag {a0,a1,a2,a3}
__device__ __align__(16) uint4 g_wprojP[16384];  // [cc 0..15][ktG 0..31][lane]
__device__ __align__(16) unsigned g_qkv[(size_t)1024 * 128 * J3];
__device__ __align__(16) unsigned g_o[(size_t)1024 * 128 * NC];

__device__ __forceinline__ unsigned f2tf(float f) {
    unsigned u; asm("cvt.rna.tf32.f32 %0, %1;" : "=r"(u) : "f"(f)); return u;
}
__device__ __forceinline__ float ex2(float x) {
    float y; asm("ex2.approx.f32 %0, %1;" : "=f"(y) : "f"(x)); return y;
}
__device__ __forceinline__ unsigned sptr(const void* p) {
    return (unsigned)__cvta_generic_to_shared(p);
}
__device__ __forceinline__ void cp16(unsigned dst, const void* src) {
    asm volatile("cp.async.ca.shared.global [%0], [%1], 16;\n" :: "r"(dst), "l"(src));
}
__device__ __forceinline__ void cp_commit() { asm volatile("cp.async.commit_group;\n"); }
template<int N> __device__ __forceinline__ void cp_wait() {
    asm volatile("cp.async.wait_group %0;\n" :: "n"(N));
}
// ldmatrix x4: mats of 8 rows x 16B; within each mat lane l <- 32-bit elem (l/4, l%4)
__device__ __forceinline__ void ldsm4(unsigned* r, unsigned addr) {
    asm volatile("ldmatrix.sync.aligned.m8n8.x4.shared.b16 {%0,%1,%2,%3}, [%4];"
        : "=r"(r[0]), "=r"(r[1]), "=r"(r[2]), "=r"(r[3]) : "r"(addr));
}
// m16n8k8 tf32: A row-major a0=[g][q] a1=[g+8][q] a2=[g][q+4] a3=[g+8][q+4]
// B col-major b0=B[q][g] b1=B[q+4][g]; C c0=(g,2q) c1=(g,2q+1) c2/c3 rows +8
__device__ __forceinline__ void mma8(float* c, const unsigned* a, unsigned b0, unsigned b1) {
    asm volatile(
        "mma.sync.aligned.m16n8k8.row.col.f32.tf32.tf32.f32 "
        "{%0,%1,%2,%3},{%4,%5,%6,%7},{%8,%9},{%0,%1,%2,%3};\n"
        : "+f"(c[0]), "+f"(c[1]), "+f"(c[2]), "+f"(c[3])
        : "r"(a[0]), "r"(a[1]), "r"(a[2]), "r"(a[3]), "r"(b0), "r"(b1));
}

// Prepack weights into fragment-major uint4 so mainloop A-loads are single LDG.128.
__global__ void k_prep(const float* __restrict__ Wqkv, const float* __restrict__ Wproj) {
    int i = blockIdx.x * 256 + threadIdx.x;       // 0..65535
    int lane = i & 31, g = lane >> 2, q = lane & 3;
    if (i < 49152) {
        int e = i >> 5, kt = e & 31, jj = e >> 5;
        int j0 = jj * 16, c0 = kt * 8;
        uint4 u;
        u.x = f2tf(Wqkv[(c0 + q) * J3 + j0 + g]);
        u.y = f2tf(Wqkv[(c0 + q) * J3 + j0 + g + 8]);
        u.z = f2tf(Wqkv[(c0 + q + 4) * J3 + j0 + g]);
        u.w = f2tf(Wqkv[(c0 + q + 4) * J3 + j0 + g + 8]);
        g_wqkvP[i] = u;
    } else {
        int ii = i - 49152;                        // 0..16383
        int e = ii >> 5, ktG = e & 31, cc = e >> 5;
        int c0 = cc * 16, k0 = ktG * 8;
        uint4 u;
        u.x = f2tf(Wproj[(k0 + q) * NC + c0 + g]);
        u.y = f2tf(Wproj[(k0 + q) * NC + c0 + g + 8]);
        u.z = f2tf(Wproj[(k0 + q + 4) * NC + c0 + g]);
        u.w = f2tf(Wproj[(k0 + q + 4) * NC + c0 + g + 8]);
        g_wprojP[ii] = u;
    }
}

// ---------- QKV projection: per (t,b,wh) CTA: D[j 768][w 64], 2 CTAs/SM
// Warp = 32 j x 64 w (2 mt x 8 nt): no A duplication, 3 j-blocks of 256.
__global__ void __launch_bounds__(256, 2) k_qkv(const float* __restrict__ x,
                                                const float* __restrict__ bqkv) {
    extern __shared__ unsigned sh[];
    unsigned* Xs = sh;                        // [256][72]
    float* Ds = (float*)(sh + 256 * 72);      // [64][132]
    const int t = blockIdx.x, b = blockIdx.y, wh = blockIdx.z;
    const int tid = threadIdx.x, lane = tid & 31, wid = tid >> 5;
    const int g = lane >> 2, q = lane & 3;
    const int wm = wid;                       // 0..7 (j-tile position)

    const float* xb = x + ((size_t)b * NC * 128 + t) * 128 + wh * 64;
    #pragma unroll
    for (int p = 0; p < 16; p++) {
        int l = tid + p * 256;
        int c = l >> 4, col = (l & 15) * 4;
        float4 v = *(const float4*)(xb + (size_t)c * 16384 + col);
        unsigned* d = Xs + c * 72 + col;
        d[0] = f2tf(v.x); d[1] = f2tf(v.y); d[2] = f2tf(v.z); d[3] = f2tf(v.w);
    }
    __syncthreads();

    for (int jb = 0; jb < 3; jb++) {
        float acc[2][8][4];
        #pragma unroll
        for (int mt = 0; mt < 2; mt++)
            #pragma unroll
            for (int nt = 0; nt < 8; nt++)
                #pragma unroll
                for (int i = 0; i < 4; i++) acc[mt][nt][i] = 0.f;

        const int jj0 = jb * 16 + wm * 2;
        #pragma unroll 2
        for (int kt = 0; kt < 32; kt++) {
            uint4 af0 = g_wqkvP[(jj0 * 32 + kt) * 32 + lane];
            uint4 af1 = g_wqkvP[((jj0 + 1) * 32 + kt) * 32 + lane];
            unsigned b0[8], b1[8];
            #pragma unroll
            for (int nt = 0; nt < 8; nt++) {
                b0[nt] = Xs[(kt * 8 + q) * 72 + nt * 8 + g];
                b1[nt] = Xs[(kt * 8 + q + 4) * 72 + nt * 8 + g];
            }
            #pragma unroll
            for (int nt = 0; nt < 8; nt++) {
                mma8(acc[0][nt], (const unsigned*)&af0, b0[nt], b1[nt]);
                mma8(acc[1][nt], (const unsigned*)&af1, b0[nt], b1[nt]);
            }
        }

        float bl[2][2];
        #pragma unroll
        for (int mt = 0; mt < 2; mt++) {
            bl[mt][0] = bqkv[jb * 256 + wm * 32 + mt * 16 + g];
            bl[mt][1] = bqkv[jb * 256 + wm * 32 + mt * 16 + g + 8];
        }

        // transpose-stage + store, in two 128-j halves (Ds holds 64w x 128j)
        #pragma unroll
        for (int half = 0; half < 2; half++) {
            __syncthreads();           // Ds free (prev contents consumed)
            if ((wm >> 2) == half) {
                int jw = (wm & 3) * 32;
                #pragma unroll
                for (int mt = 0; mt < 2; mt++)
                    #pragma unroll
                    for (int nt = 0; nt < 8; nt++) {
                        int w0 = nt * 8 + 2 * q;
                        int jl = jw + mt * 16 + g;
                        Ds[w0 * 132 + jl]           = acc[mt][nt][0] + bl[mt][0];
                        Ds[(w0 + 1) * 132 + jl]     = acc[mt][nt][1] + bl[mt][0];
                        Ds[w0 * 132 + jl + 8]       = acc[mt][nt][2] + bl[mt][1];
                        Ds[(w0 + 1) * 132 + jl + 8] = acc[mt][nt][3] + bl[mt][1];
                    }
            }
            __syncthreads();
            #pragma unroll
            for (int p = 0; p < 8; p++) {
                int l = tid + p * 256;
                int w = l >> 5, col = (l & 31) * 4;
                float4 v = *(const float4*)(Ds + w * 132 + col);
                uint4 u = { f2tf(v.x), f2tf(v.y), f2tf(v.z), f2tf(v.w) };
                *(uint4*)(g_qkv + ((size_t)((b * 128 + wh * 64 + w) * 128 + t)) * J3
                          + jb * 256 + half * 128 + col) = u;
            }
        }
    }
}

// ---------- attention per (head, s), 2 CTAs/SM (unchanged from R10)
__global__ void __launch_bounds__(256, 2) k_attn() {
    extern __shared__ unsigned sh[];
    unsigned* Qs = sh;                 // [128][68]
    unsigned* Ks = sh + 128 * 68;      // [128][68]
    unsigned* Vs = sh + 2 * 128 * 68;  // [128][72]
    const int head = blockIdx.x, s = blockIdx.y;
    const int tid = threadIdx.x, lane = tid & 31, wid = tid >> 5;
    const int g = lane >> 2, q = lane & 3;
    const int lsel = lane >> 3;
    const int arow = lane & 15, acolo = (lane >> 4) << 2;

    const unsigned* base = g_qkv + (size_t)s * 128 * J3 + head * 64;
    const int r0 = tid >> 4, l16 = tid & 15;
    for (int tt = r0; tt < 128; tt += 16) {        // group 0: Q + K
        const unsigned* row = base + (size_t)tt * J3;
        cp16(sptr(Qs + tt * 68 + l16 * 4), row + l16 * 4);
        cp16(sptr(Ks + tt * 68 + l16 * 4), row + 256 + l16 * 4);
    }
    cp_commit();
    for (int tt = r0; tt < 128; tt += 16) {        // group 1: V
        const unsigned* row = base + (size_t)tt * J3;
        cp16(sptr(Vs + tt * 72 + l16 * 4), row + 512 + l16 * 4);
    }
    cp_commit();
    cp_wait<1>();                                  // Q,K ready; V still in flight
    __syncthreads();

    const int m0 = wid * 16;
    float sa[16][4];
    #pragma unroll
    for (int nt = 0; nt < 16; nt++)
        #pragma unroll
        for (int i = 0; i < 4; i++) sa[nt][i] = 0.f;

    #pragma unroll
    for (int kt = 0; kt < 8; kt++) {
        unsigned a[4];
        ldsm4(a, sptr(Qs + (m0 + arow) * 68 + kt * 8 + acolo));
        #pragma unroll
        for (int p = 0; p < 8; p++) {
            unsigned bb[4];
            int ntl = p * 2 + (lsel >> 1);
            ldsm4(bb, sptr(Ks + (ntl * 8 + (lane & 7)) * 68 + kt * 8 + ((lsel & 1) << 2)));
            mma8(sa[p * 2],     a, bb[0], bb[1]);
            mma8(sa[p * 2 + 1], a, bb[2], bb[3]);
        }
    }

    const float k2e = 0.125f * 1.4426950408889634f;
    float mx0 = -1e30f, mx1 = -1e30f;
    #pragma unroll
    for (int nt = 0; nt < 16; nt++) {
        mx0 = fmaxf(mx0, fmaxf(sa[nt][0], sa[nt][1]));
        mx1 = fmaxf(mx1, fmaxf(sa[nt][2], sa[nt][3]));
    }
    mx0 = fmaxf(mx0, __shfl_xor_sync(0xffffffffu, mx0, 1));
    mx0 = fmaxf(mx0, __shfl_xor_sync(0xffffffffu, mx0, 2));
    mx1 = fmaxf(mx1, __shfl_xor_sync(0xffffffffu, mx1, 1));
    mx1 = fmaxf(mx1, __shfl_xor_sync(0xffffffffu, mx1, 2));
    float s0 = 0.f, s1 = 0.f;
    #pragma unroll
    for (int nt = 0; nt < 16; nt++) {
        sa[nt][0] = ex2((sa[nt][0] - mx0) * k2e);
        sa[nt][1] = ex2((sa[nt][1] - mx0) * k2e);
        sa[nt][2] = ex2((sa[nt][2] - mx1) * k2e);
        sa[nt][3] = ex2((sa[nt][3] - mx1) * k2e);
        s0 += sa[nt][0] + sa[nt][1];
        s1 += sa[nt][2] + sa[nt][3];
    }
    s0 += __shfl_xor_sync(0xffffffffu, s0, 1);
    s0 += __shfl_xor_sync(0xffffffffu, s0, 2);
    s1 += __shfl_xor_sync(0xffffffffu, s1, 1);
    s1 += __shfl_xor_sync(0xffffffffu, s1, 2);
    const float r0v = 1.f / s0, r1v = 1.f / s1;

    cp_wait<0>();                      // V ready
    __syncthreads();                   // all warps done with Qs/Ks; V visible
    unsigned* Ps = sh;                 // [128][132], overlays Qs+Ks
    #pragma unroll
    for (int nt = 0; nt < 16; nt++) {
        int cc = nt * 8 + 2 * q;
        Ps[(m0 + g) * 132 + cc]         = f2tf(sa[nt][0] * r0v);
        Ps[(m0 + g) * 132 + cc + 1]     = f2tf(sa[nt][1] * r0v);
        Ps[(m0 + g + 8) * 132 + cc]     = f2tf(sa[nt][2] * r1v);
        Ps[(m0 + g + 8) * 132 + cc + 1] = f2tf(sa[nt][3] * r1v);
    }
    __syncwarp();                      // warp reads only its own P rows

    float oa[8][4];
    #pragma unroll
    for (int nt = 0; nt < 8; nt++)
        #pragma unroll
        for (int i = 0; i < 4; i++) oa[nt][i] = 0.f;

    #pragma unroll
    for (int kt = 0; kt < 16; kt++) {
        unsigned a[4];
        ldsm4(a, sptr(Ps + (m0 + arow) * 132 + kt * 8 + acolo));
        #pragma unroll
        for (int nt = 0; nt < 8; nt++) {
            unsigned b0 = Vs[(kt * 8 + q) * 72 + nt * 8 + g];
            unsigned b1 = Vs[(kt * 8 + q + 4) * 72 + nt * 8 + g];
            mma8(oa[nt], a, b0, b1);
        }
    }

    unsigned* ob = g_o + (size_t)s * 128 * NC + head * 64;
    #pragma unroll
    for (int nt = 0; nt < 8; nt++) {
        int d0 = nt * 8 + 2 * q;
        uint2 u0 = { f2tf(oa[nt][0]), f2tf(oa[nt][1]) };
        uint2 u1 = { f2tf(oa[nt][2]), f2tf(oa[nt][3]) };
        *(uint2*)(ob + (size_t)(m0 + g) * NC + d0) = u0;
        *(uint2*)(ob + (size_t)(m0 + g + 8) * NC + d0) = u1;
    }
}

// ---------- output projection: per (t,b,wh) CTA over 64 w, 2 CTAs/SM
// Warp = 32 c x 64 w (2 mt x 8 nt): no A duplication.
__global__ void __launch_bounds__(256, 2) k_proj(const float* __restrict__ bproj,
                                                 float* __restrict__ out) {
    extern __shared__ unsigned sh[];   // 2 x [64][132]
    const int t = blockIdx.x, b = blockIdx.y, wh = blockIdx.z;
    const int tid = threadIdx.x, lane = tid & 31, wid = tid >> 5;
    const int g = lane >> 2, q = lane & 3;
    const int wm = wid;                // 0..7 (c-tile position)
    const int lsel = lane >> 3;

    #pragma unroll
    for (int kh = 0; kh < 2; kh++) {
        unsigned* shb = sh + kh * 64 * 132;
        #pragma unroll
        for (int p = 0; p < 8; p++) {
            int l = tid + p * 256;
            int w = l >> 5, col = (l & 31) * 4;
            cp16(sptr(shb + w * 132 + col),
                 g_o + ((size_t)((b * 128 + wh * 64 + w) * 128 + t)) * NC + kh * 128 + col);
        }
        cp_commit();
    }

    float acc[2][8][4];
    #pragma unroll
    for (int mt = 0; mt < 2; mt++)
        #pragma unroll
        for (int nt = 0; nt < 8; nt++)
            #pragma unroll
            for (int i = 0; i < 4; i++) acc[mt][nt][i] = 0.f;

    cp_wait<1>();
    __syncthreads();

    for (int kh = 0; kh < 2; kh++) {
        unsigned* shb = sh + kh * 64 * 132;
        #pragma unroll 2
        for (int kt = 0; kt < 16; kt++) {
            uint4 af[2];
            #pragma unroll
            for (int mt = 0; mt < 2; mt++)
                af[mt] = g_wprojP[((wm * 2 + mt) * 32 + kh * 16 + kt) * 32 + lane];
            #pragma unroll
            for (int p = 0; p < 4; p++) {
                unsigned bb[4];
                int ntl = p * 2 + (lsel >> 1);
                ldsm4(bb, sptr(shb + (ntl * 8 + (lane & 7)) * 132
                                  + kt * 8 + ((lsel & 1) << 2)));
                #pragma unroll
                for (int mt = 0; mt < 2; mt++) {
                    mma8(acc[mt][p * 2],     (const unsigned*)&af[mt], bb[0], bb[1]);
                    mma8(acc[mt][p * 2 + 1], (const unsigned*)&af[mt], bb[2], bb[3]);
                }
            }
        }
        if (kh == 0) { cp_wait<0>(); __syncthreads(); }
    }

    #pragma unroll
    for (int mt = 0; mt < 2; mt++) {
        int c0 = wm * 32 + mt * 16 + g;
        float bi0 = bproj[c0], bi1 = bproj[c0 + 8];
        #pragma unroll
        for (int nt = 0; nt < 8; nt++) {
            int w0 = wh * 64 + nt * 8 + 2 * q;
            float2 v0 = { acc[mt][nt][0] + bi0, acc[mt][nt][1] + bi0 };
            float2 v1 = { acc[mt][nt][2] + bi1, acc[mt][nt][3] + bi1 };
            *(float2*)(out + ((size_t)(b * NC + c0) * 128 + t) * 128 + w0) = v0;
            *(float2*)(out + ((size_t)(b * NC + c0 + 8) * 128 + t) * 128 + w0) = v1;
        }
    }
}

extern "C" void kernel_launch(void* const* d_in, const int* in_sizes, int n_in,
                              void* d_out, int out_size) {
    const float* x     = (const float*)d_in[0];
    const float* Wqkv  = (const float*)d_in[1];
    const float* bqkv  = (const float*)d_in[2];
    const float* Wproj = (const float*)d_in[3];
    const float* bproj = (const float*)d_in[4];
    float* out = (float*)d_out;

    cudaFuncSetAttribute(k_qkv,  cudaFuncAttributeMaxDynamicSharedMemorySize, 107520);
    cudaFuncSetAttribute(k_attn, cudaFuncAttributeMaxDynamicSharedMemorySize, 106496);
    cudaFuncSetAttribute(k_proj, cudaFuncAttributeMaxDynamicSharedMemorySize, 67584);

    k_prep<<<256, 256>>>(Wqkv, Wproj);
    k_qkv<<<dim3(128, 8, 2), 256, 107520>>>(x, bqkv);
    k_attn<<<dim3(4, 1024), 256, 106496>>>();
    k_proj<<<dim3(128, 8, 2), 256, 67584>>>(bproj, out);
}

// round 12
// speedup vs baseline: 2.5266x; 1.8453x over previous
#include <cuda_runtime.h>

#define J3 768
#define NC 256

__device__ __align__(16) uint4 g_wqkvP[24576];   // [jj 0..47][kt 0..15][lane] fp16 A-frags
__device__ __align__(16) uint4 g_wprojP[8192];   // [cc 0..15][kt 0..15][lane]
__device__ __align__(16) unsigned short g_qkv[(size_t)1024 * 128 * J3];
__device__ __align__(16) unsigned short g_o[(size_t)1024 * 128 * NC];

__device__ __forceinline__ unsigned pack2(float lo, float hi) {
    unsigned u; asm("cvt.rn.f16x2.f32 %0, %1, %2;" : "=r"(u) : "f"(hi), "f"(lo)); return u;
}
__device__ __forceinline__ float ex2(float x) {
    float y; asm("ex2.approx.f32 %0, %1;" : "=f"(y) : "f"(x)); return y;
}
__device__ __forceinline__ unsigned sptr(const void* p) {
    return (unsigned)__cvta_generic_to_shared(p);
}
__device__ __forceinline__ void cp16(unsigned dst, const void* src) {
    asm volatile("cp.async.ca.shared.global [%0], [%1], 16;\n" :: "r"(dst), "l"(src));
}
__device__ __forceinline__ void cp_commit() { asm volatile("cp.async.commit_group;\n"); }
template<int N> __device__ __forceinline__ void cp_wait() {
    asm volatile("cp.async.wait_group %0;\n" :: "n"(N));
}
__device__ __forceinline__ void ldsm4(unsigned* r, unsigned addr) {
    asm volatile("ldmatrix.sync.aligned.m8n8.x4.shared.b16 {%0,%1,%2,%3}, [%4];"
        : "=r"(r[0]), "=r"(r[1]), "=r"(r[2]), "=r"(r[3]) : "r"(addr));
}
__device__ __forceinline__ void ldsm4t(unsigned* r, unsigned addr) {
    asm volatile("ldmatrix.sync.aligned.m8n8.x4.trans.shared.b16 {%0,%1,%2,%3}, [%4];"
        : "=r"(r[0]), "=r"(r[1]), "=r"(r[2]), "=r"(r[3]) : "r"(addr));
}
// m16n8k16 fp16: A row-major a0=(g,2q,2q+1) a1=(g+8,..) a2=(g,2q+8..) a3=(g+8,2q+8..)
// B col-major b0=(k 2q,2q+1; n g) b1=(k 2q+8..; n g); C c0=(g,2q) c1=(g,2q+1) c2/c3 +8 rows
__device__ __forceinline__ void mma16(float* c, const unsigned* a, unsigned b0, unsigned b1) {
    asm volatile(
        "mma.sync.aligned.m16n8k16.row.col.f32.f16.f16.f32 "
        "{%0,%1,%2,%3},{%4,%5,%6,%7},{%8,%9},{%0,%1,%2,%3};\n"
        : "+f"(c[0]), "+f"(c[1]), "+f"(c[2]), "+f"(c[3])
        : "r"(a[0]), "r"(a[1]), "r"(a[2]), "r"(a[3]), "r"(b0), "r"(b1));
}

// Prepack weights as fp16 m16n8k16 A-fragments (one LDG.128 per warp per frag).
__global__ void k_prep(const float* __restrict__ Wqkv, const float* __restrict__ Wproj) {
    int i = blockIdx.x * 256 + threadIdx.x;       // 0..32767
    int lane = i & 31, g = lane >> 2, q = lane & 3;
    if (i < 24576) {
        int e = i >> 5, kt = e & 15, jj = e >> 4;
        int j = jj * 16 + g, c0 = kt * 16;
        uint4 u;
        u.x = pack2(Wqkv[(c0 + 2*q)     * J3 + j],     Wqkv[(c0 + 2*q + 1) * J3 + j]);
        u.y = pack2(Wqkv[(c0 + 2*q)     * J3 + j + 8], Wqkv[(c0 + 2*q + 1) * J3 + j + 8]);
        u.z = pack2(Wqkv[(c0 + 2*q + 8) * J3 + j],     Wqkv[(c0 + 2*q + 9) * J3 + j]);
        u.w = pack2(Wqkv[(c0 + 2*q + 8) * J3 + j + 8], Wqkv[(c0 + 2*q + 9) * J3 + j + 8]);
        g_wqkvP[i] = u;
    } else {
        int ii = i - 24576;                        // 0..8191
        int e = ii >> 5, kt = e & 15, cc = e >> 4;
        int c = cc * 16 + g, k0 = kt * 16;
        uint4 u;
        u.x = pack2(Wproj[(k0 + 2*q)     * NC + c],     Wproj[(k0 + 2*q + 1) * NC + c]);
        u.y = pack2(Wproj[(k0 + 2*q)     * NC + c + 8], Wproj[(k0 + 2*q + 1) * NC + c + 8]);
        u.z = pack2(Wproj[(k0 + 2*q + 8) * NC + c],     Wproj[(k0 + 2*q + 9) * NC + c]);
        u.w = pack2(Wproj[(k0 + 2*q + 8) * NC + c + 8], Wproj[(k0 + 2*q + 9) * NC + c + 8]);
        g_wprojP[ii] = u;
    }
}

// ---------- QKV projection: per (t,b,wh) CTA: D[j 768][w 64] fp16, 2 CTAs/SM
__global__ void __launch_bounds__(256, 2) k_qkv(const float* __restrict__ x,
                                                const float* __restrict__ bqkv) {
    extern __shared__ unsigned shm[];
    unsigned short* Xs = (unsigned short*)shm;    // [256 c][72] halves
    float* Ds = (float*)(shm + (256 * 72) / 2);   // [64 w][132] floats
    const int t = blockIdx.x, b = blockIdx.y, wh = blockIdx.z;
    const int tid = threadIdx.x, lane = tid & 31, wid = tid >> 5;
    const int g = lane >> 2, q = lane & 3;
    const int wm = wid;

    // B ldsm (trans) address: rows c, 16B segs along w
    const int bro = (lane & 7) + (((lane >> 3) & 1) << 3);   // row offset within 16-c chunk
    const int bco = (lane >> 4) << 3;                        // +8 halves for mats 2,3

    const float* xb = x + ((size_t)b * NC * 128 + t) * 128 + wh * 64;
    #pragma unroll
    for (int p = 0; p < 16; p++) {
        int l = tid + p * 256;
        int c = l >> 4, colw = (l & 15) * 4;
        float4 v = *(const float4*)(xb + (size_t)c * 16384 + colw);
        uint2 u = { pack2(v.x, v.y), pack2(v.z, v.w) };
        *(uint2*)(Xs + c * 72 + colw) = u;
    }
    __syncthreads();

    for (int jb = 0; jb < 3; jb++) {
        float acc[2][8][4];
        #pragma unroll
        for (int mt = 0; mt < 2; mt++)
            #pragma unroll
            for (int nt = 0; nt < 8; nt++)
                #pragma unroll
                for (int i = 0; i < 4; i++) acc[mt][nt][i] = 0.f;

        const int jj0 = jb * 16 + wm * 2;
        #pragma unroll 4
        for (int kt = 0; kt < 16; kt++) {
            uint4 af0 = g_wqkvP[(jj0 * 16 + kt) * 32 + lane];
            uint4 af1 = g_wqkvP[((jj0 + 1) * 16 + kt) * 32 + lane];
            #pragma unroll
            for (int p = 0; p < 4; p++) {
                unsigned bb[4];
                ldsm4t(bb, sptr(Xs + (kt * 16 + bro) * 72 + p * 16 + bco));
                mma16(acc[0][p * 2],     (const unsigned*)&af0, bb[0], bb[1]);
                mma16(acc[0][p * 2 + 1], (const unsigned*)&af0, bb[2], bb[3]);
                mma16(acc[1][p * 2],     (const unsigned*)&af1, bb[0], bb[1]);
                mma16(acc[1][p * 2 + 1], (const unsigned*)&af1, bb[2], bb[3]);
            }
        }

        float bl[2][2];
        #pragma unroll
        for (int mt = 0; mt < 2; mt++) {
            bl[mt][0] = bqkv[jb * 256 + wm * 32 + mt * 16 + g];
            bl[mt][1] = bqkv[jb * 256 + wm * 32 + mt * 16 + g + 8];
        }

        #pragma unroll
        for (int half = 0; half < 2; half++) {
            __syncthreads();
            if ((wm >> 2) == half) {
                int jw = (wm & 3) * 32;
                #pragma unroll
                for (int mt = 0; mt < 2; mt++)
                    #pragma unroll
                    for (int nt = 0; nt < 8; nt++) {
                        int w0 = nt * 8 + 2 * q;
                        int jl = jw + mt * 16 + g;
                        Ds[w0 * 132 + jl]           = acc[mt][nt][0] + bl[mt][0];
                        Ds[(w0 + 1) * 132 + jl]     = acc[mt][nt][1] + bl[mt][0];
                        Ds[w0 * 132 + jl + 8]       = acc[mt][nt][2] + bl[mt][1];
                        Ds[(w0 + 1) * 132 + jl + 8] = acc[mt][nt][3] + bl[mt][1];
                    }
            }
            __syncthreads();
            #pragma unroll
            for (int p = 0; p < 8; p++) {
                int l = tid + p * 256;
                int w = l >> 5, col = (l & 31) * 4;
                float4 v = *(const float4*)(Ds + w * 132 + col);
                uint2 u = { pack2(v.x, v.y), pack2(v.z, v.w) };
                *(uint2*)(g_qkv + ((size_t)((b * 128 + wh * 64 + w) * 128 + t)) * J3
                          + jb * 256 + half * 128 + col) = u;
            }
        }
    }
}

// ---------- attention per (head, s), fp16, 2 CTAs/SM
__global__ void __launch_bounds__(256, 2) k_attn() {
    extern __shared__ unsigned shm[];
    unsigned short* Qs = (unsigned short*)shm;     // [128][72]
    unsigned short* Ks = Qs + 128 * 72;            // [128][72]
    unsigned short* Vs = Qs + 2 * 128 * 72;        // [128][72]
    unsigned short* Ps = Qs;                       // [128][136], overlays Qs+Ks
    const int head = blockIdx.x, s = blockIdx.y;
    const int tid = threadIdx.x, lane = tid & 31, wid = tid >> 5;
    const int g = lane >> 2, q = lane & 3;
    const int m0 = wid * 16;
    const int arow = lane & 15, aco = (lane >> 4) << 3;              // A ldsm
    const int kro = (lane & 7) + ((lane >> 4) << 3);                 // K/Os non-trans rows
    const int kco = (((lane >> 3) & 1) << 3);
    const int vro = (lane & 7) + (((lane >> 3) & 1) << 3);           // V trans rows
    const int vco = (lane >> 4) << 3;

    const unsigned short* base = g_qkv + (size_t)s * 128 * J3 + head * 64;
    const int r0 = tid >> 3, sg = tid & 7;         // 32 rows/pass, 8 segs/row
    #pragma unroll
    for (int p = 0; p < 4; p++) {                  // group 0: Q + K
        int tt = r0 + p * 32;
        const unsigned short* row = base + (size_t)tt * J3;
        cp16(sptr(Qs + tt * 72 + sg * 8), row + sg * 8);
        cp16(sptr(Ks + tt * 72 + sg * 8), row + 256 + sg * 8);
    }
    cp_commit();
    #pragma unroll
    for (int p = 0; p < 4; p++) {                  // group 1: V
        int tt = r0 + p * 32;
        cp16(sptr(Vs + tt * 72 + sg * 8), base + (size_t)tt * J3 + 512 + sg * 8);
    }
    cp_commit();
    cp_wait<1>();
    __syncthreads();

    float sa[16][4];
    #pragma unroll
    for (int nt = 0; nt < 16; nt++)
        #pragma unroll
        for (int i = 0; i < 4; i++) sa[nt][i] = 0.f;

    #pragma unroll
    for (int kt = 0; kt < 4; kt++) {
        unsigned a[4];
        ldsm4(a, sptr(Qs + (m0 + arow) * 72 + kt * 16 + aco));
        #pragma unroll
        for (int p = 0; p < 8; p++) {
            unsigned bb[4];
            ldsm4(bb, sptr(Ks + (p * 16 + kro) * 72 + kt * 16 + kco));
            mma16(sa[p * 2],     a, bb[0], bb[1]);
            mma16(sa[p * 2 + 1], a, bb[2], bb[3]);
        }
    }

    // softmax: rows g (sa[][0,1]) and g+8 (sa[][2,3]); reduce across quad (q)
    const float k2e = 0.125f * 1.4426950408889634f;
    float mx0 = -1e30f, mx1 = -1e30f;
    #pragma unroll
    for (int nt = 0; nt < 16; nt++) {
        mx0 = fmaxf(mx0, fmaxf(sa[nt][0], sa[nt][1]));
        mx1 = fmaxf(mx1, fmaxf(sa[nt][2], sa[nt][3]));
    }
    mx0 = fmaxf(mx0, __shfl_xor_sync(0xffffffffu, mx0, 1));
    mx0 = fmaxf(mx0, __shfl_xor_sync(0xffffffffu, mx0, 2));
    mx1 = fmaxf(mx1, __shfl_xor_sync(0xffffffffu, mx1, 1));
    mx1 = fmaxf(mx1, __shfl_xor_sync(0xffffffffu, mx1, 2));
    float s0 = 0.f, s1 = 0.f;
    #pragma unroll
    for (int nt = 0; nt < 16; nt++) {
        sa[nt][0] = ex2((sa[nt][0] - mx0) * k2e);
        sa[nt][1] = ex2((sa[nt][1] - mx0) * k2e);
        sa[nt][2] = ex2((sa[nt][2] - mx1) * k2e);
        sa[nt][3] = ex2((sa[nt][3] - mx1) * k2e);
        s0 += sa[nt][0] + sa[nt][1];
        s1 += sa[nt][2] + sa[nt][3];
    }
    s0 += __shfl_xor_sync(0xffffffffu, s0, 1);
    s0 += __shfl_xor_sync(0xffffffffu, s0, 2);
    s1 += __shfl_xor_sync(0xffffffffu, s1, 1);
    s1 += __shfl_xor_sync(0xffffffffu, s1, 2);
    const float r0v = 1.f / s0, r1v = 1.f / s1;

    cp_wait<0>();                      // V ready
    __syncthreads();                   // all warps done reading Qs/Ks
    #pragma unroll
    for (int nt = 0; nt < 16; nt++) {
        int cc = nt * 8 + 2 * q;
        *(unsigned*)(Ps + (m0 + g) * 136 + cc)     = pack2(sa[nt][0] * r0v, sa[nt][1] * r0v);
        *(unsigned*)(Ps + (m0 + g + 8) * 136 + cc) = pack2(sa[nt][2] * r1v, sa[nt][3] * r1v);
    }
    __syncwarp();                      // warp reads only its own P rows

    float oa[8][4];
    #pragma unroll
    for (int nt = 0; nt < 8; nt++)
        #pragma unroll
        for (int i = 0; i < 4; i++) oa[nt][i] = 0.f;

    #pragma unroll
    for (int kt = 0; kt < 8; kt++) {
        unsigned a[4];
        ldsm4(a, sptr(Ps + (m0 + arow) * 136 + kt * 16 + aco));
        #pragma unroll
        for (int p = 0; p < 4; p++) {
            unsigned bb[4];
            ldsm4t(bb, sptr(Vs + (kt * 16 + vro) * 72 + p * 16 + vco));
            mma16(oa[p * 2],     a, bb[0], bb[1]);
            mma16(oa[p * 2 + 1], a, bb[2], bb[3]);
        }
    }

    unsigned short* ob = g_o + (size_t)s * 128 * NC + head * 64;
    #pragma unroll
    for (int nt = 0; nt < 8; nt++) {
        int d0 = nt * 8 + 2 * q;
        *(unsigned*)(ob + (size_t)(m0 + g) * NC + d0)     = pack2(oa[nt][0], oa[nt][1]);
        *(unsigned*)(ob + (size_t)(m0 + g + 8) * NC + d0) = pack2(oa[nt][2], oa[nt][3]);
    }
}

// ---------- output projection: per (t,b,wh) CTA over 64 w, fp16 operands, 2 CTAs/SM
__global__ void __launch_bounds__(256, 2) k_proj(const float* __restrict__ bproj,
                                                 float* __restrict__ out) {
    extern __shared__ unsigned shm[];
    unsigned short* Os = (unsigned short*)shm;    // [64 w][264] halves
    const int t = blockIdx.x, b = blockIdx.y, wh = blockIdx.z;
    const int tid = threadIdx.x, lane = tid & 31, wid = tid >> 5;
    const int g = lane >> 2, q = lane & 3;
    const int wm = wid;
    const int kro = (lane & 7) + ((lane >> 4) << 3);
    const int kco = (((lane >> 3) & 1) << 3);

    #pragma unroll
    for (int p = 0; p < 8; p++) {
        int l = tid + p * 256;
        int w = l >> 5, seg = l & 31;
        cp16(sptr(Os + w * 264 + seg * 8),
             g_o + ((size_t)((b * 128 + wh * 64 + w) * 128 + t)) * NC + seg * 8);
    }
    cp_commit();

    float acc[2][8][4];
    #pragma unroll
    for (int mt = 0; mt < 2; mt++)
        #pragma unroll
        for (int nt = 0; nt < 8; nt++)
            #pragma unroll
            for (int i = 0; i < 4; i++) acc[mt][nt][i] = 0.f;

    cp_wait<0>();
    __syncthreads();

    #pragma unroll 4
    for (int kt = 0; kt < 16; kt++) {
        uint4 af[2];
        #pragma unroll
        for (int mt = 0; mt < 2; mt++)
            af[mt] = g_wprojP[((wm * 2 + mt) * 16 + kt) * 32 + lane];
        #pragma unroll
        for (int p = 0; p < 4; p++) {
            unsigned bb[4];
            ldsm4(bb, sptr(Os + (p * 16 + kro) * 264 + kt * 16 + kco));
            #pragma unroll
            for (int mt = 0; mt < 2; mt++) {
                mma16(acc[mt][p * 2],     (const unsigned*)&af[mt], bb[0], bb[1]);
                mma16(acc[mt][p * 2 + 1], (const unsigned*)&af[mt], bb[2], bb[3]);
            }
        }
    }

    #pragma unroll
    for (int mt = 0; mt < 2; mt++) {
        int c0 = wm * 32 + mt * 16 + g;
        float bi0 = bproj[c0], bi1 = bproj[c0 + 8];
        #pragma unroll
        for (int nt = 0; nt < 8; nt++) {
            int w0 = wh * 64 + nt * 8 + 2 * q;
            float2 v0 = { acc[mt][nt][0] + bi0, acc[mt][nt][1] + bi0 };
            float2 v1 = { acc[mt][nt][2] + bi1, acc[mt][nt][3] + bi1 };
            *(float2*)(out + ((size_t)(b * NC + c0) * 128 + t) * 128 + w0) = v0;
            *(float2*)(out + ((size_t)(b * NC + c0 + 8) * 128 + t) * 128 + w0) = v1;
        }
    }
}

extern "C" void kernel_launch(void* const* d_in, const int* in_sizes, int n_in,
                              void* d_out, int out_size) {
    const float* x     = (const float*)d_in[0];
    const float* Wqkv  = (const float*)d_in[1];
    const float* bqkv  = (const float*)d_in[2];
    const float* Wproj = (const float*)d_in[3];
    const float* bproj = (const float*)d_in[4];
    float* out = (float*)d_out;

    cudaFuncSetAttribute(k_qkv,  cudaFuncAttributeMaxDynamicSharedMemorySize, 70656);
    cudaFuncSetAttribute(k_attn, cudaFuncAttributeMaxDynamicSharedMemorySize, 55296);
    cudaFuncSetAttribute(k_proj, cudaFuncAttributeMaxDynamicSharedMemorySize, 33792);

    k_prep<<<128, 256>>>(Wqkv, Wproj);
    k_qkv<<<dim3(128, 8, 2), 256, 70656>>>(x, bqkv);
    k_attn<<<dim3(4, 1024), 256, 55296>>>();
    k_proj<<<dim3(128, 8, 2), 256, 33792>>>(bproj, out);
}